// round 16
// baseline (speedup 1.0000x reference)
#include <cuda_runtime.h>
#include <cuda_fp16.h>
#include <math.h>
#include <stdint.h>

#define B_  4
#define N_  1024
#define C_  512
#define H_  8
#define HD_ 64
#define E_  16384
#define FF_ 2048
#define LOG2E 1.4426950408889634f

// ---------------- scratch ----------------------------------------------------
__device__ uint8_t g_rel8[B_ * N_ * N_];
__device__ __half g_h  [B_ * N_ * C_];
__device__ __half g_q  [B_ * N_ * C_];
__device__ __half g_k  [B_ * N_ * C_];
__device__ __half g_v  [B_ * N_ * C_];
__device__ __half g_att[B_ * N_ * C_];
__device__ float  g_res[B_ * N_ * C_];
__device__ __half g_h2 [B_ * N_ * C_];
__device__ __half g_mid[B_ * N_ * FF_];
__device__ __half g_wqT[C_ * C_];
__device__ __half g_wkT[C_ * C_];
__device__ __half g_wvT[C_ * C_];
__device__ __half g_woT[C_ * C_];
__device__ __half g_f1T[FF_ * C_];
__device__ __half g_f2T[C_ * FF_];

// ---------------- helpers -----------------------------------------------------
__device__ __forceinline__ uint32_t h2_as_u32(__half2 h) { return *(uint32_t*)&h; }

__device__ __forceinline__ void mma_f16(float* c, const uint32_t* a, const uint32_t* b) {
    asm volatile(
        "mma.sync.aligned.m16n8k16.row.col.f32.f16.f16.f32 "
        "{%0,%1,%2,%3}, {%4,%5,%6,%7}, {%8,%9}, {%0,%1,%2,%3};\n"
        : "+f"(c[0]), "+f"(c[1]), "+f"(c[2]), "+f"(c[3])
        : "r"(a[0]), "r"(a[1]), "r"(a[2]), "r"(a[3]), "r"(b[0]), "r"(b[1]));
}

__device__ __forceinline__ void ldsm4(uint32_t* r, uint32_t addr) {
    asm volatile("ldmatrix.sync.aligned.m8n8.x4.shared.b16 {%0,%1,%2,%3}, [%4];\n"
                 : "=r"(r[0]), "=r"(r[1]), "=r"(r[2]), "=r"(r[3]) : "r"(addr));
}

__device__ __forceinline__ void ldsm4t(uint32_t* r, uint32_t addr) {
    asm volatile("ldmatrix.sync.aligned.m8n8.x4.trans.shared.b16 {%0,%1,%2,%3}, [%4];\n"
                 : "=r"(r[0]), "=r"(r[1]), "=r"(r[2]), "=r"(r[3]) : "r"(addr));
}

__device__ __forceinline__ void cp16(uint32_t dst, const void* src) {
    asm volatile("cp.async.cg.shared.global [%0], [%1], 16;\n" :: "r"(dst), "l"(src));
}
__device__ __forceinline__ void cp_commit() { asm volatile("cp.async.commit_group;\n"); }
template <int NMAX>
__device__ __forceinline__ void cp_wait() { asm volatile("cp.async.wait_group %0;\n" :: "n"(NMAX)); }

// ---------------- batched weight transpose + fp16 convert -----------------------
__global__ __launch_bounds__(256)
void transpose_all_kernel(const float* __restrict__ q_w, const float* __restrict__ k_w,
                          const float* __restrict__ v_w, const float* __restrict__ o_w,
                          const float* __restrict__ f1_w, const float* __restrict__ f2_w) {
    __shared__ float t[32][33];
    int blk = blockIdx.x;
    const float* src;
    __half* dst;
    int R, Ccols, ti;
    if (blk < 1024) {
        int m = blk >> 8; ti = blk & 255;
        src = (m == 0) ? q_w : (m == 1) ? k_w : (m == 2) ? v_w : o_w;
        dst = (m == 0) ? g_wqT : (m == 1) ? g_wkT : (m == 2) ? g_wvT : g_woT;
        R = C_; Ccols = C_;
    } else if (blk < 2048) {
        ti = blk - 1024; src = f1_w; dst = g_f1T; R = C_; Ccols = FF_;
    } else {
        ti = blk - 2048; src = f2_w; dst = g_f2T; R = FF_; Ccols = C_;
    }
    int ct = Ccols >> 5;
    int c0 = (ti % ct) * 32, r0 = (ti / ct) * 32;
    int tx = threadIdx.x & 31, ty = threadIdx.x >> 5;
#pragma unroll
    for (int i = 0; i < 4; i++)
        t[ty + i * 8][tx] = src[(size_t)(r0 + ty + i * 8) * Ccols + c0 + tx];
    __syncthreads();
#pragma unroll
    for (int i = 0; i < 4; i++)
        dst[(size_t)(c0 + ty + i * 8) * R + r0 + tx] = __float2half_rn(t[tx][ty + i * 8]);
}

// ---------------- rel8 map ---------------------------------------------------------
__global__ void init_rel8_kernel(uint4* __restrict__ rel16) {
    int idx = blockIdx.x * blockDim.x + threadIdx.x;
    int total = (B_ * N_ * N_) / 16;
    uint4 z = make_uint4(0, 0, 0, 0);
    for (int i = idx; i < total; i += gridDim.x * blockDim.x) rel16[i] = z;
}

__global__ void scatter_edges8_kernel(const int* __restrict__ edge_index,
                                      const int* __restrict__ edge_type,
                                      unsigned int* __restrict__ rel8w) {
    int idx = blockIdx.x * blockDim.x + threadIdx.x;
    if (idx >= B_ * E_) return;
    int b = idx / E_;
    int e = idx - b * E_;
    int s = edge_index[b * 2 * E_ + e];
    int t = edge_index[b * 2 * E_ + E_ + e];
    int r = edge_type[b * E_ + e];
    if (s < 0 || s >= N_ || t < 0 || t >= N_) return;
    unsigned int cell = (unsigned int)(b * N_ * N_ + s * N_ + t);
    unsigned int word = cell >> 2, sh = (cell & 3u) * 8u;
    unsigned int val = (unsigned int)(r + 1);
    unsigned int old = rel8w[word];
    while (((old >> sh) & 0xffu) < val) {
        unsigned int assumed = old;
        unsigned int newv = (old & ~(0xffu << sh)) | (val << sh);
        old = atomicCAS(&rel8w[word], assumed, newv);
        if (old == assumed) break;
    }
}

// ---------------- layernorm: 4 rows/CTA, 64 thr/row, 8 floats/thread ---------------
__global__ __launch_bounds__(256)
void ln_kernel(const float* __restrict__ x, const float* __restrict__ gma,
               const float* __restrict__ bta, __half* __restrict__ y) {
    int tid = threadIdx.x;
    int rsel = tid >> 6;                    // 0..3
    int t = tid & 63;                       // 64 threads per row
    int row = blockIdx.x * 4 + rsel;
    int lane = tid & 31, warp = tid >> 5;   // warps 2r, 2r+1 belong to row r
    const float* xr = x + (size_t)row * C_;
    float4 xa = *(const float4*)&xr[t * 8];
    float4 xb = *(const float4*)&xr[t * 8 + 4];
    float s = xa.x + xa.y + xa.z + xa.w + xb.x + xb.y + xb.z + xb.w;
    float q = xa.x * xa.x + xa.y * xa.y + xa.z * xa.z + xa.w * xa.w
            + xb.x * xb.x + xb.y * xb.y + xb.z * xb.z + xb.w * xb.w;
#pragma unroll
    for (int o = 16; o > 0; o >>= 1) {
        s += __shfl_xor_sync(0xffffffffu, s, o);
        q += __shfl_xor_sync(0xffffffffu, q, o);
    }
    __shared__ float ws[8], wq[8], stat[8];
    if (lane == 0) { ws[warp] = s; wq[warp] = q; }
    __syncthreads();
    if (tid < 4) {
        float s2 = ws[tid * 2] + ws[tid * 2 + 1];
        float q2 = wq[tid * 2] + wq[tid * 2 + 1];
        float mean = s2 * (1.0f / C_);
        float var = q2 * (1.0f / C_) - mean * mean;
        stat[tid * 2]     = mean;
        stat[tid * 2 + 1] = rsqrtf(var + 1e-5f);
    }
    __syncthreads();
    float mean = stat[rsel * 2], inv = stat[rsel * 2 + 1];
    float4 ga = *(const float4*)&gma[t * 8];
    float4 gb = *(const float4*)&gma[t * 8 + 4];
    float4 ba = *(const float4*)&bta[t * 8];
    float4 bb = *(const float4*)&bta[t * 8 + 4];
    uint4 o;
    o.x = h2_as_u32(__floats2half2_rn((xa.x - mean) * inv * ga.x + ba.x, (xa.y - mean) * inv * ga.y + ba.y));
    o.y = h2_as_u32(__floats2half2_rn((xa.z - mean) * inv * ga.z + ba.z, (xa.w - mean) * inv * ga.w + ba.w));
    o.z = h2_as_u32(__floats2half2_rn((xb.x - mean) * inv * gb.x + bb.x, (xb.y - mean) * inv * gb.y + bb.y));
    o.w = h2_as_u32(__floats2half2_rn((xb.z - mean) * inv * gb.z + bb.z, (xb.w - mean) * inv * gb.w + bb.w));
    *(uint4*)&y[(size_t)row * C_ + t * 8] = o;
}

// ---------------- pipelined fp16 GEMM (BK=64, 2-stage) -----------------------------
enum { EPI_BIAS = 0, EPI_GELU = 1, EPI_RES = 2 };
#define WST 72

template <int EPI>
__global__ __launch_bounds__(256, 2)
void mm_tc(const __half* __restrict__ Abase,
           const __half* __restrict__ W0, const __half* __restrict__ W1,
           const __half* __restrict__ W2,
           const float* __restrict__ bi0, const float* __restrict__ bi1,
           const float* __restrict__ bi2,
           const float* __restrict__ res,
           void* __restrict__ O0, void* __restrict__ O1, void* __restrict__ O2,
           int K, int lda, int ldb, int ldc) {
    constexpr int BM = 128, BN = 128, BK = 64;
    constexpr int MI = 4, NI = 4, WARPS_M = 2;
    constexpr int WM = MI * 16, WN = NI * 8;
    constexpr int AS_B = BM * WST * 2;
    constexpr int STG_B = AS_B + BN * WST * 2;

    extern __shared__ char smc[];
    uint32_t sbase = (uint32_t)__cvta_generic_to_shared(smc);

    int tid = threadIdx.x;
    int warp = tid >> 5, lane = tid & 31;
    int gid = lane >> 2, tig = lane & 3;
    int wm = warp % WARPS_M, wn = warp / WARPS_M;
    int m0 = blockIdx.y * BM, n0 = blockIdx.x * BN;

    int z = blockIdx.z;
    const __half* A   = Abase;
    const __half* Bm  = (z == 0) ? W0 : ((z == 1) ? W1 : W2);
    const float* bias = (z == 0) ? bi0 : ((z == 1) ? bi1 : bi2);
    void* Co          = (z == 0) ? O0 : ((z == 1) ? O1 : O2);

    int li = lane >> 3;
    uint32_t a_off = ((((li & 1) * 8) + (lane & 7)) * WST + (li >> 1) * 8) * 2;
    uint32_t b_off = ((((li >> 1) * 8) + (lane & 7)) * WST + (li & 1) * 8) * 2;

    float acc[MI][NI][4] = {};

    auto load_tile = [&](int stage, int k0) {
        uint32_t ab = sbase + stage * STG_B;
#pragma unroll
        for (int i = 0; i < 4; i++) {
            int f = tid + i * 256;
            int r = f >> 3, c = (f & 7) << 3;
            cp16(ab + (r * WST + c) * 2, A + (size_t)(m0 + r) * lda + k0 + c);
        }
        uint32_t bb = sbase + stage * STG_B + AS_B;
#pragma unroll
        for (int i = 0; i < 4; i++) {
            int f = tid + i * 256;
            int r = f >> 3, c = (f & 7) << 3;
            cp16(bb + (r * WST + c) * 2, Bm + (size_t)(n0 + r) * ldb + k0 + c);
        }
    };

    int KT = K / BK;
    load_tile(0, 0); cp_commit();

    for (int kt = 0; kt < KT; kt++) {
        int cur = kt & 1;
        if (kt + 1 < KT) {
            load_tile(cur ^ 1, (kt + 1) * BK);
            cp_commit();
            cp_wait<1>();
        } else {
            cp_wait<0>();
        }
        __syncthreads();

        uint32_t a_s = sbase + cur * STG_B + (wm * WM) * WST * 2 + a_off;
        uint32_t b_s = sbase + cur * STG_B + AS_B + (wn * WN) * WST * 2 + b_off;
#pragma unroll
        for (int ks = 0; ks < 4; ks++) {
            uint32_t af[MI][4];
#pragma unroll
            for (int mi = 0; mi < MI; mi++)
                ldsm4(af[mi], a_s + mi * (16 * WST * 2) + ks * 32);
            uint32_t bf[NI / 2][4];
#pragma unroll
            for (int p = 0; p < NI / 2; p++)
                ldsm4(bf[p], b_s + p * (16 * WST * 2) + ks * 32);
#pragma unroll
            for (int mi = 0; mi < MI; mi++)
#pragma unroll
                for (int ni = 0; ni < NI; ni++)
                    mma_f16(acc[mi][ni], af[mi], &bf[ni >> 1][(ni & 1) * 2]);
        }
        __syncthreads();
    }

#pragma unroll
    for (int mi = 0; mi < MI; mi++) {
#pragma unroll
        for (int ni = 0; ni < NI; ni++) {
            int r = m0 + wm * WM + mi * 16 + gid;
            int c = n0 + wn * WN + ni * 8 + tig * 2;
#pragma unroll
            for (int e2 = 0; e2 < 2; e2++) {
                int rr = r + e2 * 8;
                float v0 = acc[mi][ni][e2 * 2];
                float v1 = acc[mi][ni][e2 * 2 + 1];
                float2 bb = *(const float2*)&bias[c];
                v0 += bb.x; v1 += bb.y;
                if (EPI == EPI_GELU) {
                    v0 = 0.5f * v0 * (1.0f + erff(v0 * 0.70710678118654752f));
                    v1 = 0.5f * v1 * (1.0f + erff(v1 * 0.70710678118654752f));
                }
                if (EPI == EPI_RES) {
                    float2 rr2 = *(const float2*)&res[(size_t)rr * ldc + c];
                    *(float2*)&((float*)Co)[(size_t)rr * ldc + c] = make_float2(v0 + rr2.x, v1 + rr2.y);
                } else {
                    *(__half2*)&((__half*)Co)[(size_t)rr * ldc + c] = __floats2half2_rn(v0, v1);
                }
            }
        }
    }
}

// ---------------- fused flash attention: P in regs, rel prefetch -------------------
#define FST 72
#define KVB (64 * FST * 2)

__global__ __launch_bounds__(256, 2)
void flash_attn_kernel(const __half* __restrict__ q, const __half* __restrict__ k,
                       const __half* __restrict__ v, const uint8_t* __restrict__ rel8,
                       const float* __restrict__ table, __half* __restrict__ att) {
    extern __shared__ char smc[];
    float* tbl = (float*)(smc + 128 * FST * 2 + 6 * KVB);

    uint32_t sb  = (uint32_t)__cvta_generic_to_shared(smc);
    uint32_t Q_u = sb;
    uint32_t K_u = sb + 128 * FST * 2;
    uint32_t V_u = K_u + 3 * KVB;

    int tid = threadIdx.x;
    int warp = tid >> 5, lane = tid & 31;
    int gid = lane >> 2, tig = lane & 3;
    int bh = blockIdx.y, b = bh >> 3, h = bh & 7;
    int m0 = blockIdx.x * 128;
    int wrow = warp * 16;

    const __half* Q  = q + (size_t)b * N_ * C_ + h * HD_;
    const __half* Kp = k + (size_t)b * N_ * C_ + h * HD_;
    const __half* Vp = v + (size_t)b * N_ * C_ + h * HD_;
    const uint8_t* relb = rel8 + (size_t)b * N_ * N_;

    if (tid < 9) tbl[tid] = (tid == 0) ? 0.0f : table[(tid - 1) * H_ + h] * LOG2E;

    auto load_kv = [&](int stage, int kn0) {
        uint32_t kb = K_u + stage * KVB;
        uint32_t vb = V_u + stage * KVB;
#pragma unroll
        for (int i = 0; i < 2; i++) {
            int f = tid + i * 256;
            int r = f >> 3, c = (f & 7) << 3;
            cp16(kb + (r * FST + c) * 2, Kp + (size_t)(kn0 + r) * C_ + c);
            cp16(vb + (r * FST + c) * 2, Vp + (size_t)(kn0 + r) * C_ + c);
        }
    };

#pragma unroll
    for (int i = 0; i < 4; i++) {
        int f = tid + i * 256;
        int r = f >> 3, c = (f & 7) << 3;
        cp16(Q_u + (r * FST + c) * 2, Q + (size_t)(m0 + r) * C_ + c);
    }
    cp_commit();
    load_kv(0, 0);   cp_commit();
    load_kv(1, 64);  cp_commit();
    cp_wait<2>();
    __syncthreads();

    int li = lane >> 3;
    uint32_t a_off = ((((li & 1) * 8) + (lane & 7)) * FST + (li >> 1) * 8) * 2;
    uint32_t b_off = ((((li >> 1) * 8) + (lane & 7)) * FST + (li & 1) * 8) * 2;

    uint32_t qf[4][4];
    {
        uint32_t qbase = Q_u + wrow * FST * 2 + a_off;
#pragma unroll
        for (int ks = 0; ks < 4; ks++)
            ldsm4(qf[ks], qbase + ks * 32);
    }

    float acc_o[8][4] = {};
    float mprev[2] = {-INFINITY, -INFINITY};
    float lsum[2] = {0.0f, 0.0f};

    const int KT = N_ / 64;
    for (int kt = 0; kt < KT; kt++) {
        int cur = kt % 3;
        int kn0 = kt * 64;
        if (kt < KT - 1) cp_wait<1>(); else cp_wait<0>();
        __syncthreads();
        if (kt + 2 < KT) { load_kv((kt + 2) % 3, (kt + 2) * 64); cp_commit(); }

        // prefetch rel8 bytes for this tile (independent of MMA below)
        uchar2 rvp[8][2];
#pragma unroll
        for (int ni = 0; ni < 8; ni++)
#pragma unroll
            for (int e2 = 0; e2 < 2; e2++) {
                int rr = wrow + gid + e2 * 8;
                int col = kn0 + ni * 8 + tig * 2;
                rvp[ni][e2] = *(const uchar2*)&relb[(size_t)(m0 + rr) * N_ + col];
            }

        // S = Q K^T
        float acc_s[8][4] = {};
        {
            uint32_t kb = K_u + cur * KVB + b_off;
#pragma unroll
            for (int ks = 0; ks < 4; ks++) {
                uint32_t bf[4][4];
#pragma unroll
                for (int nb = 0; nb < 4; nb++)
                    ldsm4(bf[nb], kb + nb * (16 * FST * 2) + ks * 32);
#pragma unroll
                for (int ni = 0; ni < 8; ni++)
                    mma_f16(acc_s[ni], qf[ks], &bf[ni >> 1][(ni & 1) * 2]);
            }
        }

        // scale(+log2e) + rel bias + row max
        float rmax[2] = {-INFINITY, -INFINITY};
#pragma unroll
        for (int ni = 0; ni < 8; ni++)
#pragma unroll
            for (int e2 = 0; e2 < 2; e2++) {
                float v0 = acc_s[ni][e2 * 2]     * (0.125f * LOG2E) + tbl[rvp[ni][e2].x];
                float v1 = acc_s[ni][e2 * 2 + 1] * (0.125f * LOG2E) + tbl[rvp[ni][e2].y];
                acc_s[ni][e2 * 2] = v0;
                acc_s[ni][e2 * 2 + 1] = v1;
                rmax[e2] = fmaxf(rmax[e2], fmaxf(v0, v1));
            }
#pragma unroll
        for (int e2 = 0; e2 < 2; e2++) {
            rmax[e2] = fmaxf(rmax[e2], __shfl_xor_sync(0xffffffffu, rmax[e2], 1));
            rmax[e2] = fmaxf(rmax[e2], __shfl_xor_sync(0xffffffffu, rmax[e2], 2));
        }

        // exp2 + row sum; P packed into A-fragments
        float nm[2], fr[2], rsum[2] = {0.0f, 0.0f};
#pragma unroll
        for (int e2 = 0; e2 < 2; e2++) {
            nm[e2] = fmaxf(mprev[e2], rmax[e2]);
            fr[e2] = exp2f(mprev[e2] - nm[e2]);
        }
        uint32_t ph[8][2];
#pragma unroll
        for (int ni = 0; ni < 8; ni++)
#pragma unroll
            for (int e2 = 0; e2 < 2; e2++) {
                float p0 = exp2f(acc_s[ni][e2 * 2]     - nm[e2]);
                float p1 = exp2f(acc_s[ni][e2 * 2 + 1] - nm[e2]);
                rsum[e2] += p0 + p1;
                ph[ni][e2] = h2_as_u32(__floats2half2_rn(p0, p1));
            }
#pragma unroll
        for (int e2 = 0; e2 < 2; e2++) {
            rsum[e2] += __shfl_xor_sync(0xffffffffu, rsum[e2], 1);
            rsum[e2] += __shfl_xor_sync(0xffffffffu, rsum[e2], 2);
            lsum[e2] = lsum[e2] * fr[e2] + rsum[e2];
            mprev[e2] = nm[e2];
        }

        // rescale acc_o
#pragma unroll
        for (int ni = 0; ni < 8; ni++) {
            acc_o[ni][0] *= fr[0]; acc_o[ni][1] *= fr[0];
            acc_o[ni][2] *= fr[1]; acc_o[ni][3] *= fr[1];
        }

        // O += P V
        {
            uint32_t vb = V_u + cur * KVB + a_off;
#pragma unroll
            for (int j = 0; j < 4; j++) {
                uint32_t af[4] = { ph[2 * j][0], ph[2 * j][1], ph[2 * j + 1][0], ph[2 * j + 1][1] };
                uint32_t bf[4][4];
#pragma unroll
                for (int nb = 0; nb < 4; nb++)
                    ldsm4t(bf[nb], vb + j * (16 * FST * 2) + nb * 32);
#pragma unroll
                for (int ni = 0; ni < 8; ni++)
                    mma_f16(acc_o[ni], af, &bf[ni >> 1][(ni & 1) * 2]);
            }
        }
    }

    // finalize
#pragma unroll
    for (int ni = 0; ni < 8; ni++)
#pragma unroll
        for (int e2 = 0; e2 < 2; e2++) {
            int rr = wrow + gid + e2 * 8;
            int col = ni * 8 + tig * 2;
            float inv = 1.0f / lsum[e2];
            *(__half2*)&att[((size_t)b * N_ + m0 + rr) * C_ + h * HD_ + col] =
                __floats2half2_rn(acc_o[ni][e2 * 2] * inv, acc_o[ni][e2 * 2 + 1] * inv);
        }
}

// ---------------- launch -----------------------------------------------------------
extern "C" void kernel_launch(void* const* d_in, const int* in_sizes, int n_in,
                              void* d_out, int out_size) {
    const float* x     = (const float*)d_in[0];
    const int*   eidx  = (const int*)  d_in[1];
    const int*   etype = (const int*)  d_in[2];
    const float* q_w   = (const float*)d_in[3];
    const float* q_b   = (const float*)d_in[4];
    const float* k_w   = (const float*)d_in[5];
    const float* k_b   = (const float*)d_in[6];
    const float* v_w   = (const float*)d_in[7];
    const float* v_b   = (const float*)d_in[8];
    const float* o_w   = (const float*)d_in[9];
    const float* o_b   = (const float*)d_in[10];
    const float* table = (const float*)d_in[11];
    const float* ln1_g = (const float*)d_in[12];
    const float* ln1_b = (const float*)d_in[13];
    const float* ln2_g = (const float*)d_in[14];
    const float* ln2_b = (const float*)d_in[15];
    const float* f1_w  = (const float*)d_in[16];
    const float* f1_b  = (const float*)d_in[17];
    const float* f2_w  = (const float*)d_in[18];
    const float* f2_b  = (const float*)d_in[19];
    float* out = (float*)d_out;

    void *p_rel8, *p_h, *p_q, *p_k, *p_v, *p_att, *p_res, *p_h2, *p_mid;
    void *p_wq, *p_wk, *p_wv, *p_wo, *p_f1, *p_f2;
    cudaGetSymbolAddress(&p_rel8, g_rel8);
    cudaGetSymbolAddress(&p_h,   g_h);
    cudaGetSymbolAddress(&p_q,   g_q);
    cudaGetSymbolAddress(&p_k,   g_k);
    cudaGetSymbolAddress(&p_v,   g_v);
    cudaGetSymbolAddress(&p_att, g_att);
    cudaGetSymbolAddress(&p_res, g_res);
    cudaGetSymbolAddress(&p_h2,  g_h2);
    cudaGetSymbolAddress(&p_mid, g_mid);
    cudaGetSymbolAddress(&p_wq,  g_wqT);
    cudaGetSymbolAddress(&p_wk,  g_wkT);
    cudaGetSymbolAddress(&p_wv,  g_wvT);
    cudaGetSymbolAddress(&p_wo,  g_woT);
    cudaGetSymbolAddress(&p_f1,  g_f1T);
    cudaGetSymbolAddress(&p_f2,  g_f2T);

    const int SMEM_MM    = 2 * (256 * WST * 2);
    const int SMEM_FLASH = 128 * FST * 2 + 6 * KVB + 16 * 4;
    cudaFuncSetAttribute(mm_tc<EPI_BIAS>, cudaFuncAttributeMaxDynamicSharedMemorySize, SMEM_MM);
    cudaFuncSetAttribute(mm_tc<EPI_RES>,  cudaFuncAttributeMaxDynamicSharedMemorySize, SMEM_MM);
    cudaFuncSetAttribute(mm_tc<EPI_GELU>, cudaFuncAttributeMaxDynamicSharedMemorySize, SMEM_MM);
    cudaFuncSetAttribute(flash_attn_kernel, cudaFuncAttributeMaxDynamicSharedMemorySize, SMEM_FLASH);

    static cudaStream_t s1 = nullptr;
    static cudaEvent_t ev_fork = nullptr, ev_rel = nullptr;
    if (s1 == nullptr) {
        cudaStreamCreateWithFlags(&s1, cudaStreamNonBlocking);
        cudaEventCreateWithFlags(&ev_fork, cudaEventDisableTiming);
        cudaEventCreateWithFlags(&ev_rel,  cudaEventDisableTiming);
    }

    const int rows = B_ * N_;
    __half* fh  = (__half*)p_h;  __half* fq = (__half*)p_q;  __half* fk = (__half*)p_k;
    __half* fv  = (__half*)p_v;
    __half* fatt = (__half*)p_att; float* fres = (float*)p_res;
    __half* fh2 = (__half*)p_h2; __half* fmid = (__half*)p_mid;

    // fork: rel8 path on s1
    cudaEventRecord(ev_fork, 0);
    cudaStreamWaitEvent(s1, ev_fork, 0);
    init_rel8_kernel<<<1024, 256, 0, s1>>>((uint4*)p_rel8);
    scatter_edges8_kernel<<<(B_ * E_) / 256, 256, 0, s1>>>(eidx, etype, (unsigned int*)p_rel8);
    cudaEventRecord(ev_rel, s1);

    // main chain
    transpose_all_kernel<<<3072, 256>>>(q_w, k_w, v_w, o_w, f1_w, f2_w);
    ln_kernel<<<rows / 4, 256>>>(x, ln1_g, ln1_b, fh);
    mm_tc<EPI_BIAS><<<dim3(C_ / 128, rows / 128, 3), 256, SMEM_MM>>>(
        fh, (__half*)p_wq, (__half*)p_wk, (__half*)p_wv, q_b, k_b, v_b, nullptr,
        fq, fk, fv, C_, C_, C_, C_);

    cudaStreamWaitEvent(0, ev_rel, 0);
    flash_attn_kernel<<<dim3(N_ / 128, B_ * H_), 256, SMEM_FLASH>>>(
        fq, fk, fv, (const uint8_t*)p_rel8, table, fatt);
    mm_tc<EPI_RES><<<dim3(C_ / 128, rows / 128, 1), 256, SMEM_MM>>>(
        fatt, (__half*)p_wo, nullptr, nullptr, o_b, nullptr, nullptr, x,
        fres, nullptr, nullptr, C_, C_, C_, C_);
    ln_kernel<<<rows / 4, 256>>>(fres, ln2_g, ln2_b, fh2);
    mm_tc<EPI_GELU><<<dim3(FF_ / 128, rows / 128, 1), 256, SMEM_MM>>>(
        fh2, (__half*)p_f1, nullptr, nullptr, f1_b, nullptr, nullptr, nullptr,
        fmid, nullptr, nullptr, C_, C_, C_, FF_);
    mm_tc<EPI_RES><<<dim3(C_ / 128, rows / 128, 1), 256, SMEM_MM>>>(
        fmid, (__half*)p_f2, nullptr, nullptr, f2_b, nullptr, nullptr, fres,
        out, nullptr, nullptr, FF_, FF_, FF_, C_);
}

// round 17
// speedup vs baseline: 1.0131x; 1.0131x over previous
#include <cuda_runtime.h>
#include <cuda_fp16.h>
#include <math.h>
#include <stdint.h>

#define B_  4
#define N_  1024
#define C_  512
#define H_  8
#define HD_ 64
#define E_  16384
#define FF_ 2048
#define LOG2E 1.4426950408889634f

// ---------------- scratch ----------------------------------------------------
__device__ uint8_t g_rel8[B_ * N_ * N_];
__device__ __half g_h  [B_ * N_ * C_];
__device__ __half g_q  [B_ * N_ * C_];
__device__ __half g_k  [B_ * N_ * C_];
__device__ __half g_v  [B_ * N_ * C_];
__device__ __half g_att[B_ * N_ * C_];
__device__ float  g_res[B_ * N_ * C_];
__device__ __half g_h2 [B_ * N_ * C_];
__device__ __half g_mid[B_ * N_ * FF_];
__device__ __half g_wqT[C_ * C_];
__device__ __half g_wkT[C_ * C_];
__device__ __half g_wvT[C_ * C_];
__device__ __half g_woT[C_ * C_];
__device__ __half g_f1T[FF_ * C_];
__device__ __half g_f2T[C_ * FF_];

// ---------------- helpers -----------------------------------------------------
__device__ __forceinline__ uint32_t h2_as_u32(__half2 h) { return *(uint32_t*)&h; }

__device__ __forceinline__ void mma_f16(float* c, const uint32_t* a, const uint32_t* b) {
    asm volatile(
        "mma.sync.aligned.m16n8k16.row.col.f32.f16.f16.f32 "
        "{%0,%1,%2,%3}, {%4,%5,%6,%7}, {%8,%9}, {%0,%1,%2,%3};\n"
        : "+f"(c[0]), "+f"(c[1]), "+f"(c[2]), "+f"(c[3])
        : "r"(a[0]), "r"(a[1]), "r"(a[2]), "r"(a[3]), "r"(b[0]), "r"(b[1]));
}

__device__ __forceinline__ void ldsm4(uint32_t* r, uint32_t addr) {
    asm volatile("ldmatrix.sync.aligned.m8n8.x4.shared.b16 {%0,%1,%2,%3}, [%4];\n"
                 : "=r"(r[0]), "=r"(r[1]), "=r"(r[2]), "=r"(r[3]) : "r"(addr));
}

__device__ __forceinline__ void ldsm4t(uint32_t* r, uint32_t addr) {
    asm volatile("ldmatrix.sync.aligned.m8n8.x4.trans.shared.b16 {%0,%1,%2,%3}, [%4];\n"
                 : "=r"(r[0]), "=r"(r[1]), "=r"(r[2]), "=r"(r[3]) : "r"(addr));
}

__device__ __forceinline__ void cp16(uint32_t dst, const void* src) {
    asm volatile("cp.async.cg.shared.global [%0], [%1], 16;\n" :: "r"(dst), "l"(src));
}
__device__ __forceinline__ void cp_commit() { asm volatile("cp.async.commit_group;\n"); }
template <int NMAX>
__device__ __forceinline__ void cp_wait() { asm volatile("cp.async.wait_group %0;\n" :: "n"(NMAX)); }

// ---------------- batched weight transpose + fp16 convert -----------------------
__global__ __launch_bounds__(256)
void transpose_all_kernel(const float* __restrict__ q_w, const float* __restrict__ k_w,
                          const float* __restrict__ v_w, const float* __restrict__ o_w,
                          const float* __restrict__ f1_w, const float* __restrict__ f2_w) {
    __shared__ float t[32][33];
    int blk = blockIdx.x;
    const float* src;
    __half* dst;
    int R, Ccols, ti;
    if (blk < 1024) {
        int m = blk >> 8; ti = blk & 255;
        src = (m == 0) ? q_w : (m == 1) ? k_w : (m == 2) ? v_w : o_w;
        dst = (m == 0) ? g_wqT : (m == 1) ? g_wkT : (m == 2) ? g_wvT : g_woT;
        R = C_; Ccols = C_;
    } else if (blk < 2048) {
        ti = blk - 1024; src = f1_w; dst = g_f1T; R = C_; Ccols = FF_;
    } else {
        ti = blk - 2048; src = f2_w; dst = g_f2T; R = FF_; Ccols = C_;
    }
    int ct = Ccols >> 5;
    int c0 = (ti % ct) * 32, r0 = (ti / ct) * 32;
    int tx = threadIdx.x & 31, ty = threadIdx.x >> 5;
#pragma unroll
    for (int i = 0; i < 4; i++)
        t[ty + i * 8][tx] = src[(size_t)(r0 + ty + i * 8) * Ccols + c0 + tx];
    __syncthreads();
#pragma unroll
    for (int i = 0; i < 4; i++)
        dst[(size_t)(c0 + ty + i * 8) * R + r0 + tx] = __float2half_rn(t[tx][ty + i * 8]);
}

// ---------------- rel8 map ---------------------------------------------------------
__global__ void init_rel8_kernel(uint4* __restrict__ rel16) {
    int idx = blockIdx.x * blockDim.x + threadIdx.x;
    int total = (B_ * N_ * N_) / 16;
    uint4 z = make_uint4(0, 0, 0, 0);
    for (int i = idx; i < total; i += gridDim.x * blockDim.x) rel16[i] = z;
}

__global__ void scatter_edges8_kernel(const int* __restrict__ edge_index,
                                      const int* __restrict__ edge_type,
                                      unsigned int* __restrict__ rel8w) {
    int idx = blockIdx.x * blockDim.x + threadIdx.x;
    if (idx >= B_ * E_) return;
    int b = idx / E_;
    int e = idx - b * E_;
    int s = edge_index[b * 2 * E_ + e];
    int t = edge_index[b * 2 * E_ + E_ + e];
    int r = edge_type[b * E_ + e];
    if (s < 0 || s >= N_ || t < 0 || t >= N_) return;
    unsigned int cell = (unsigned int)(b * N_ * N_ + s * N_ + t);
    unsigned int word = cell >> 2, sh = (cell & 3u) * 8u;
    unsigned int val = (unsigned int)(r + 1);
    unsigned int old = rel8w[word];
    while (((old >> sh) & 0xffu) < val) {
        unsigned int assumed = old;
        unsigned int newv = (old & ~(0xffu << sh)) | (val << sh);
        old = atomicCAS(&rel8w[word], assumed, newv);
        if (old == assumed) break;
    }
}

// ---------------- layernorm: float4, 2 rows per CTA --------------------------------
__global__ __launch_bounds__(256)
void ln_kernel(const float* __restrict__ x, const float* __restrict__ gma,
               const float* __restrict__ bta, __half* __restrict__ y) {
    int tid = threadIdx.x;
    int rsel = tid >> 7;                    // 0 or 1
    int t = tid & 127;                      // 128 threads per row, float4 each
    int row = blockIdx.x * 2 + rsel;
    int lane = tid & 31, warp = tid >> 5;   // warps 0-3 row0, 4-7 row1
    const float* xr = x + (size_t)row * C_;
    float4 xv = *(const float4*)&xr[t * 4];
    float s = xv.x + xv.y + xv.z + xv.w;
    float q = xv.x * xv.x + xv.y * xv.y + xv.z * xv.z + xv.w * xv.w;
#pragma unroll
    for (int o = 16; o > 0; o >>= 1) {
        s += __shfl_xor_sync(0xffffffffu, s, o);
        q += __shfl_xor_sync(0xffffffffu, q, o);
    }
    __shared__ float ws[8], wq[8], stat[4];
    if (lane == 0) { ws[warp] = s; wq[warp] = q; }
    __syncthreads();
    if (tid < 2) {
        float s2 = ws[tid * 4] + ws[tid * 4 + 1] + ws[tid * 4 + 2] + ws[tid * 4 + 3];
        float q2 = wq[tid * 4] + wq[tid * 4 + 1] + wq[tid * 4 + 2] + wq[tid * 4 + 3];
        float mean = s2 * (1.0f / C_);
        float var = q2 * (1.0f / C_) - mean * mean;
        stat[tid * 2]     = mean;
        stat[tid * 2 + 1] = rsqrtf(var + 1e-5f);
    }
    __syncthreads();
    float mean = stat[rsel * 2], inv = stat[rsel * 2 + 1];
    float4 g = *(const float4*)&gma[t * 4];
    float4 bb = *(const float4*)&bta[t * 4];
    __half2 h0 = __floats2half2_rn((xv.x - mean) * inv * g.x + bb.x, (xv.y - mean) * inv * g.y + bb.y);
    __half2 h1 = __floats2half2_rn((xv.z - mean) * inv * g.z + bb.z, (xv.w - mean) * inv * g.w + bb.w);
    *(uint2*)&y[(size_t)row * C_ + t * 4] = make_uint2(h2_as_u32(h0), h2_as_u32(h1));
}

// ---------------- pipelined fp16 GEMM (BK=64, 2-stage) -----------------------------
enum { EPI_BIAS = 0, EPI_GELU = 1, EPI_RES = 2 };
#define WST 72

template <int EPI>
__global__ __launch_bounds__(256, 2)
void mm_tc(const __half* __restrict__ Abase,
           const __half* __restrict__ W0, const __half* __restrict__ W1,
           const __half* __restrict__ W2,
           const float* __restrict__ bi0, const float* __restrict__ bi1,
           const float* __restrict__ bi2,
           const float* __restrict__ res,
           void* __restrict__ O0, void* __restrict__ O1, void* __restrict__ O2,
           int K, int lda, int ldb, int ldc) {
    constexpr int BM = 128, BN = 128, BK = 64;
    constexpr int MI = 4, NI = 4, WARPS_M = 2;
    constexpr int WM = MI * 16, WN = NI * 8;
    constexpr int AS_B = BM * WST * 2;
    constexpr int STG_B = AS_B + BN * WST * 2;

    extern __shared__ char smc[];
    uint32_t sbase = (uint32_t)__cvta_generic_to_shared(smc);

    int tid = threadIdx.x;
    int warp = tid >> 5, lane = tid & 31;
    int gid = lane >> 2, tig = lane & 3;
    int wm = warp % WARPS_M, wn = warp / WARPS_M;
    int m0 = blockIdx.y * BM, n0 = blockIdx.x * BN;

    int z = blockIdx.z;
    const __half* A   = Abase;
    const __half* Bm  = (z == 0) ? W0 : ((z == 1) ? W1 : W2);
    const float* bias = (z == 0) ? bi0 : ((z == 1) ? bi1 : bi2);
    void* Co          = (z == 0) ? O0 : ((z == 1) ? O1 : O2);

    int li = lane >> 3;
    uint32_t a_off = ((((li & 1) * 8) + (lane & 7)) * WST + (li >> 1) * 8) * 2;
    uint32_t b_off = ((((li >> 1) * 8) + (lane & 7)) * WST + (li & 1) * 8) * 2;

    float acc[MI][NI][4] = {};

    auto load_tile = [&](int stage, int k0) {
        uint32_t ab = sbase + stage * STG_B;
#pragma unroll
        for (int i = 0; i < 4; i++) {
            int f = tid + i * 256;
            int r = f >> 3, c = (f & 7) << 3;
            cp16(ab + (r * WST + c) * 2, A + (size_t)(m0 + r) * lda + k0 + c);
        }
        uint32_t bb = sbase + stage * STG_B + AS_B;
#pragma unroll
        for (int i = 0; i < 4; i++) {
            int f = tid + i * 256;
            int r = f >> 3, c = (f & 7) << 3;
            cp16(bb + (r * WST + c) * 2, Bm + (size_t)(n0 + r) * ldb + k0 + c);
        }
    };

    int KT = K / BK;
    load_tile(0, 0); cp_commit();

    for (int kt = 0; kt < KT; kt++) {
        int cur = kt & 1;
        if (kt + 1 < KT) {
            load_tile(cur ^ 1, (kt + 1) * BK);
            cp_commit();
            cp_wait<1>();
        } else {
            cp_wait<0>();
        }
        __syncthreads();

        uint32_t a_s = sbase + cur * STG_B + (wm * WM) * WST * 2 + a_off;
        uint32_t b_s = sbase + cur * STG_B + AS_B + (wn * WN) * WST * 2 + b_off;
#pragma unroll
        for (int ks = 0; ks < 4; ks++) {
            uint32_t af[MI][4];
#pragma unroll
            for (int mi = 0; mi < MI; mi++)
                ldsm4(af[mi], a_s + mi * (16 * WST * 2) + ks * 32);
            uint32_t bf[NI / 2][4];
#pragma unroll
            for (int p = 0; p < NI / 2; p++)
                ldsm4(bf[p], b_s + p * (16 * WST * 2) + ks * 32);
#pragma unroll
            for (int mi = 0; mi < MI; mi++)
#pragma unroll
                for (int ni = 0; ni < NI; ni++)
                    mma_f16(acc[mi][ni], af[mi], &bf[ni >> 1][(ni & 1) * 2]);
        }
        __syncthreads();
    }

#pragma unroll
    for (int mi = 0; mi < MI; mi++) {
#pragma unroll
        for (int ni = 0; ni < NI; ni++) {
            int r = m0 + wm * WM + mi * 16 + gid;
            int c = n0 + wn * WN + ni * 8 + tig * 2;
#pragma unroll
            for (int e2 = 0; e2 < 2; e2++) {
                int rr = r + e2 * 8;
                float v0 = acc[mi][ni][e2 * 2];
                float v1 = acc[mi][ni][e2 * 2 + 1];
                float2 bb = *(const float2*)&bias[c];
                v0 += bb.x; v1 += bb.y;
                if (EPI == EPI_GELU) {
                    v0 = 0.5f * v0 * (1.0f + erff(v0 * 0.70710678118654752f));
                    v1 = 0.5f * v1 * (1.0f + erff(v1 * 0.70710678118654752f));
                }
                if (EPI == EPI_RES) {
                    float2 rr2 = *(const float2*)&res[(size_t)rr * ldc + c];
                    *(float2*)&((float*)Co)[(size_t)rr * ldc + c] = make_float2(v0 + rr2.x, v1 + rr2.y);
                } else {
                    *(__half2*)&((__half*)Co)[(size_t)rr * ldc + c] = __floats2half2_rn(v0, v1);
                }
            }
        }
    }
}

// ---------------- fused flash attention: P in registers (FA2 reuse) ----------------
#define FST 72
#define KVB (64 * FST * 2)

__global__ __launch_bounds__(256, 2)
void flash_attn_kernel(const __half* __restrict__ q, const __half* __restrict__ k,
                       const __half* __restrict__ v, const uint8_t* __restrict__ rel8,
                       const float* __restrict__ table, __half* __restrict__ att) {
    extern __shared__ char smc[];
    float* tbl = (float*)(smc + 128 * FST * 2 + 6 * KVB);

    uint32_t sb  = (uint32_t)__cvta_generic_to_shared(smc);
    uint32_t Q_u = sb;                       // Q staging only
    uint32_t K_u = sb + 128 * FST * 2;
    uint32_t V_u = K_u + 3 * KVB;

    int tid = threadIdx.x;
    int warp = tid >> 5, lane = tid & 31;
    int gid = lane >> 2, tig = lane & 3;
    int bh = blockIdx.y, b = bh >> 3, h = bh & 7;
    int m0 = blockIdx.x * 128;
    int wrow = warp * 16;

    const __half* Q  = q + (size_t)b * N_ * C_ + h * HD_;
    const __half* Kp = k + (size_t)b * N_ * C_ + h * HD_;
    const __half* Vp = v + (size_t)b * N_ * C_ + h * HD_;
    const uint8_t* relb = rel8 + (size_t)b * N_ * N_;

    if (tid < 9) tbl[tid] = (tid == 0) ? 0.0f : table[(tid - 1) * H_ + h] * LOG2E;

    auto load_kv = [&](int stage, int kn0) {
        uint32_t kb = K_u + stage * KVB;
        uint32_t vb = V_u + stage * KVB;
#pragma unroll
        for (int i = 0; i < 2; i++) {
            int f = tid + i * 256;
            int r = f >> 3, c = (f & 7) << 3;
            cp16(kb + (r * FST + c) * 2, Kp + (size_t)(kn0 + r) * C_ + c);
            cp16(vb + (r * FST + c) * 2, Vp + (size_t)(kn0 + r) * C_ + c);
        }
    };

#pragma unroll
    for (int i = 0; i < 4; i++) {
        int f = tid + i * 256;
        int r = f >> 3, c = (f & 7) << 3;
        cp16(Q_u + (r * FST + c) * 2, Q + (size_t)(m0 + r) * C_ + c);
    }
    cp_commit();
    load_kv(0, 0);   cp_commit();
    load_kv(1, 64);  cp_commit();
    cp_wait<2>();
    __syncthreads();

    int li = lane >> 3;
    uint32_t a_off = ((((li & 1) * 8) + (lane & 7)) * FST + (li >> 1) * 8) * 2;
    uint32_t b_off = ((((li >> 1) * 8) + (lane & 7)) * FST + (li & 1) * 8) * 2;

    uint32_t qf[4][4];
    {
        uint32_t qbase = Q_u + wrow * FST * 2 + a_off;
#pragma unroll
        for (int ks = 0; ks < 4; ks++)
            ldsm4(qf[ks], qbase + ks * 32);
    }

    float acc_o[8][4] = {};
    float mprev[2] = {-INFINITY, -INFINITY};
    float lsum[2] = {0.0f, 0.0f};

    const int KT = N_ / 64;
    for (int kt = 0; kt < KT; kt++) {
        int cur = kt % 3;
        int kn0 = kt * 64;
        if (kt < KT - 1) cp_wait<1>(); else cp_wait<0>();
        __syncthreads();
        if (kt + 2 < KT) { load_kv((kt + 2) % 3, (kt + 2) * 64); cp_commit(); }

        // S = Q K^T
        float acc_s[8][4] = {};
        {
            uint32_t kb = K_u + cur * KVB + b_off;
#pragma unroll
            for (int ks = 0; ks < 4; ks++) {
                uint32_t bf[4][4];
#pragma unroll
                for (int nb = 0; nb < 4; nb++)
                    ldsm4(bf[nb], kb + nb * (16 * FST * 2) + ks * 32);
#pragma unroll
                for (int ni = 0; ni < 8; ni++)
                    mma_f16(acc_s[ni], qf[ks], &bf[ni >> 1][(ni & 1) * 2]);
            }
        }

        // scale(+log2e) + rel bias + row max
        float rmax[2] = {-INFINITY, -INFINITY};
#pragma unroll
        for (int ni = 0; ni < 8; ni++)
#pragma unroll
            for (int e2 = 0; e2 < 2; e2++) {
                int rr = wrow + gid + e2 * 8;
                int col = kn0 + ni * 8 + tig * 2;
                uchar2 rv = *(const uchar2*)&relb[(size_t)(m0 + rr) * N_ + col];
                float v0 = acc_s[ni][e2 * 2]     * (0.125f * LOG2E) + tbl[rv.x];
                float v1 = acc_s[ni][e2 * 2 + 1] * (0.125f * LOG2E) + tbl[rv.y];
                acc_s[ni][e2 * 2] = v0;
                acc_s[ni][e2 * 2 + 1] = v1;
                rmax[e2] = fmaxf(rmax[e2], fmaxf(v0, v1));
            }
#pragma unroll
        for (int e2 = 0; e2 < 2; e2++) {
            rmax[e2] = fmaxf(rmax[e2], __shfl_xor_sync(0xffffffffu, rmax[e2], 1));
            rmax[e2] = fmaxf(rmax[e2], __shfl_xor_sync(0xffffffffu, rmax[e2], 2));
        }

        // exp2 + row sum; P packed directly into A-fragments (no smem round-trip)
        float nm[2], fr[2], rsum[2] = {0.0f, 0.0f};
#pragma unroll
        for (int e2 = 0; e2 < 2; e2++) {
            nm[e2] = fmaxf(mprev[e2], rmax[e2]);
            fr[e2] = exp2f(mprev[e2] - nm[e2]);
        }
        uint32_t ph[8][2];
#pragma unroll
        for (int ni = 0; ni < 8; ni++)
#pragma unroll
            for (int e2 = 0; e2 < 2; e2++) {
                float p0 = exp2f(acc_s[ni][e2 * 2]     - nm[e2]);
                float p1 = exp2f(acc_s[ni][e2 * 2 + 1] - nm[e2]);
                rsum[e2] += p0 + p1;
                ph[ni][e2] = h2_as_u32(__floats2half2_rn(p0, p1));
            }
#pragma unroll
        for (int e2 = 0; e2 < 2; e2++) {
            rsum[e2] += __shfl_xor_sync(0xffffffffu, rsum[e2], 1);
            rsum[e2] += __shfl_xor_sync(0xffffffffu, rsum[e2], 2);
            lsum[e2] = lsum[e2] * fr[e2] + rsum[e2];
            mprev[e2] = nm[e2];
        }

        // rescale acc_o
#pragma unroll
        for (int ni = 0; ni < 8; ni++) {
            acc_o[ni][0] *= fr[0]; acc_o[ni][1] *= fr[0];
            acc_o[ni][2] *= fr[1]; acc_o[ni][3] *= fr[1];
        }

        // O += P V  (A = ph fragments; k-step j covers kv cols 16j..16j+15)
        {
            uint32_t vb = V_u + cur * KVB + a_off;
#pragma unroll
            for (int j = 0; j < 4; j++) {
                uint32_t af[4] = { ph[2 * j][0], ph[2 * j][1], ph[2 * j + 1][0], ph[2 * j + 1][1] };
                uint32_t bf[4][4];
#pragma unroll
                for (int nb = 0; nb < 4; nb++)
                    ldsm4t(bf[nb], vb + j * (16 * FST * 2) + nb * 32);
#pragma unroll
                for (int ni = 0; ni < 8; ni++)
                    mma_f16(acc_o[ni], af, &bf[ni >> 1][(ni & 1) * 2]);
            }
        }
    }

    // finalize
#pragma unroll
    for (int ni = 0; ni < 8; ni++)
#pragma unroll
        for (int e2 = 0; e2 < 2; e2++) {
            int rr = wrow + gid + e2 * 8;
            int col = ni * 8 + tig * 2;
            float inv = 1.0f / lsum[e2];
            *(__half2*)&att[((size_t)b * N_ + m0 + rr) * C_ + h * HD_ + col] =
                __floats2half2_rn(acc_o[ni][e2 * 2] * inv, acc_o[ni][e2 * 2 + 1] * inv);
        }
}

// ---------------- launch -----------------------------------------------------------
extern "C" void kernel_launch(void* const* d_in, const int* in_sizes, int n_in,
                              void* d_out, int out_size) {
    const float* x     = (const float*)d_in[0];
    const int*   eidx  = (const int*)  d_in[1];
    const int*   etype = (const int*)  d_in[2];
    const float* q_w   = (const float*)d_in[3];
    const float* q_b   = (const float*)d_in[4];
    const float* k_w   = (const float*)d_in[5];
    const float* k_b   = (const float*)d_in[6];
    const float* v_w   = (const float*)d_in[7];
    const float* v_b   = (const float*)d_in[8];
    const float* o_w   = (const float*)d_in[9];
    const float* o_b   = (const float*)d_in[10];
    const float* table = (const float*)d_in[11];
    const float* ln1_g = (const float*)d_in[12];
    const float* ln1_b = (const float*)d_in[13];
    const float* ln2_g = (const float*)d_in[14];
    const float* ln2_b = (const float*)d_in[15];
    const float* f1_w  = (const float*)d_in[16];
    const float* f1_b  = (const float*)d_in[17];
    const float* f2_w  = (const float*)d_in[18];
    const float* f2_b  = (const float*)d_in[19];
    float* out = (float*)d_out;

    void *p_rel8, *p_h, *p_q, *p_k, *p_v, *p_att, *p_res, *p_h2, *p_mid;
    void *p_wq, *p_wk, *p_wv, *p_wo, *p_f1, *p_f2;
    cudaGetSymbolAddress(&p_rel8, g_rel8);
    cudaGetSymbolAddress(&p_h,   g_h);
    cudaGetSymbolAddress(&p_q,   g_q);
    cudaGetSymbolAddress(&p_k,   g_k);
    cudaGetSymbolAddress(&p_v,   g_v);
    cudaGetSymbolAddress(&p_att, g_att);
    cudaGetSymbolAddress(&p_res, g_res);
    cudaGetSymbolAddress(&p_h2,  g_h2);
    cudaGetSymbolAddress(&p_mid, g_mid);
    cudaGetSymbolAddress(&p_wq,  g_wqT);
    cudaGetSymbolAddress(&p_wk,  g_wkT);
    cudaGetSymbolAddress(&p_wv,  g_wvT);
    cudaGetSymbolAddress(&p_wo,  g_woT);
    cudaGetSymbolAddress(&p_f1,  g_f1T);
    cudaGetSymbolAddress(&p_f2,  g_f2T);

    const int SMEM_MM    = 2 * (256 * WST * 2);
    const int SMEM_FLASH = 128 * FST * 2 + 6 * KVB + 16 * 4;
    cudaFuncSetAttribute(mm_tc<EPI_BIAS>, cudaFuncAttributeMaxDynamicSharedMemorySize, SMEM_MM);
    cudaFuncSetAttribute(mm_tc<EPI_RES>,  cudaFuncAttributeMaxDynamicSharedMemorySize, SMEM_MM);
    cudaFuncSetAttribute(mm_tc<EPI_GELU>, cudaFuncAttributeMaxDynamicSharedMemorySize, SMEM_MM);
    cudaFuncSetAttribute(flash_attn_kernel, cudaFuncAttributeMaxDynamicSharedMemorySize, SMEM_FLASH);

    static cudaStream_t s1 = nullptr;
    static cudaEvent_t ev_fork = nullptr, ev_rel = nullptr;
    if (s1 == nullptr) {
        cudaStreamCreateWithFlags(&s1, cudaStreamNonBlocking);
        cudaEventCreateWithFlags(&ev_fork, cudaEventDisableTiming);
        cudaEventCreateWithFlags(&ev_rel,  cudaEventDisableTiming);
    }

    const int rows = B_ * N_;
    __half* fh  = (__half*)p_h;  __half* fq = (__half*)p_q;  __half* fk = (__half*)p_k;
    __half* fv  = (__half*)p_v;
    __half* fatt = (__half*)p_att; float* fres = (float*)p_res;
    __half* fh2 = (__half*)p_h2; __half* fmid = (__half*)p_mid;

    // fork: rel8 path on s1
    cudaEventRecord(ev_fork, 0);
    cudaStreamWaitEvent(s1, ev_fork, 0);
    init_rel8_kernel<<<1024, 256, 0, s1>>>((uint4*)p_rel8);
    scatter_edges8_kernel<<<(B_ * E_) / 256, 256, 0, s1>>>(eidx, etype, (unsigned int*)p_rel8);
    cudaEventRecord(ev_rel, s1);

    // main chain
    transpose_all_kernel<<<3072, 256>>>(q_w, k_w, v_w, o_w, f1_w, f2_w);
    ln_kernel<<<rows / 2, 256>>>(x, ln1_g, ln1_b, fh);
    mm_tc<EPI_BIAS><<<dim3(C_ / 128, rows / 128, 3), 256, SMEM_MM>>>(
        fh, (__half*)p_wq, (__half*)p_wk, (__half*)p_wv, q_b, k_b, v_b, nullptr,
        fq, fk, fv, C_, C_, C_, C_);

    cudaStreamWaitEvent(0, ev_rel, 0);
    flash_attn_kernel<<<dim3(N_ / 128, B_ * H_), 256, SMEM_FLASH>>>(
        fq, fk, fv, (const uint8_t*)p_rel8, table, fatt);
    mm_tc<EPI_RES><<<dim3(C_ / 128, rows / 128, 1), 256, SMEM_MM>>>(
        fatt, (__half*)p_wo, nullptr, nullptr, o_b, nullptr, nullptr, x,
        fres, nullptr, nullptr, C_, C_, C_, C_);
    ln_kernel<<<rows / 2, 256>>>(fres, ln2_g, ln2_b, fh2);
    mm_tc<EPI_GELU><<<dim3(FF_ / 128, rows / 128, 1), 256, SMEM_MM>>>(
        fh2, (__half*)p_f1, nullptr, nullptr, f1_b, nullptr, nullptr, nullptr,
        fmid, nullptr, nullptr, C_, C_, C_, FF_);
    mm_tc<EPI_RES><<<dim3(C_ / 128, rows / 128, 1), 256, SMEM_MM>>>(
        fmid, (__half*)p_f2, nullptr, nullptr, f2_b, nullptr, nullptr, fres,
        out, nullptr, nullptr, FF_, FF_, FF_, C_);
}